// round 12
// baseline (speedup 1.0000x reference)
#include <cuda_runtime.h>
#include <cuda_bf16.h>
#include <mma.h>
#include <cstdint>

using namespace nvcuda;

#define BVAL 8
#define CVAL 256
#define HW   4096
#define NTOK 4097
#define NPAD 4352          // 17 tiles of 256
#define NTILES 17
#define TOPKN 150
#define QOFF ((size_t)BVAL*HW*CVAL)   // offset of queries in d_out

// ---------------- scratch (static device globals; no allocation) ----------------
__device__ __align__(256) __nv_bfloat16 g_concath[(size_t)BVAL*CVAL*NPAD];  // concat bf16 [c][n]
__device__ __align__(256) float g_concatT [(size_t)BVAL*NPAD*CVAL];         // concat^T fp32 [n][c]
__device__ __align__(256) float g_proj  [(size_t)BVAL*HW*CVAL];             // proj fp32
__device__ __align__(256) __nv_bfloat16 g_projh[(size_t)BVAL*HW*CVAL];      // proj bf16
__device__ __align__(256) float g_values[(size_t)BVAL*NTOK*CVAL];           // values fp32
__device__ __align__(256) __nv_bfloat16 g_attnh[(size_t)BVAL*HW*NPAD];      // logits bf16
__device__ __align__(256) float g_tilemax[(size_t)BVAL*HW*NTILES];          // per-tile row max
__device__ __align__(256) float g_attn_exe[(size_t)BVAL*HW];                // exact fp32 exe column

// ---------------- cp.async helper ----------------
__device__ __forceinline__ void cpa16(void* dst, const void* src) {
    unsigned d = (unsigned)__cvta_generic_to_shared(dst);
    asm volatile("cp.async.cg.shared.global [%0], [%1], 16;\n" :: "r"(d), "l"(src));
}

// ---------------- merged concat: bf16 [c][n] + fp32 transpose [n][c], img read once ------
__global__ __launch_bounds__(256) void k_concat2(const float* __restrict__ img,
                                                 const float* __restrict__ exe) {
    __shared__ float tile[32][33];
    int b = blockIdx.z;
    int n0 = blockIdx.x * 32, c0 = blockIdx.y * 32;
    int tx = threadIdx.x & 31, ty = threadIdx.x >> 5;   // 32 x 8
    #pragma unroll
    for (int j = 0; j < 4; j++) {
        int c = c0 + ty + j * 8, n = n0 + tx;
        float v;
        if (n < HW) v = img[((size_t)b * CVAL + c) * HW + n];
        else        v = (n == HW) ? 1.2f * exe[b * CVAL + c] : 0.0f;
        tile[ty + j * 8][tx] = v;
        g_concath[((size_t)b * CVAL + c) * NPAD + n] = __float2bfloat16(v);
    }
    __syncthreads();
    #pragma unroll
    for (int j = 0; j < 4; j++) {
        int n = n0 + ty + j * 8, c = c0 + tx;
        g_concatT[((size_t)b * NPAD + n) * CVAL + c] = tile[tx][ty + j * 8];
    }
}

// ---------------- fp32 SIMT GEMM microkernel ----------------
__device__ __forceinline__ void gemm_tile_compute(const float (*As)[132], const float (*Bs)[128],
                                                  float (&acc)[8][8], int tx, int ty) {
    #pragma unroll
    for (int k = 0; k < 8; k++) {
        float4 a0 = *(const float4*)&As[k][ty * 4];
        float4 a1 = *(const float4*)&As[k][64 + ty * 4];
        float4 b0 = *(const float4*)&Bs[k][tx * 4];
        float4 b1 = *(const float4*)&Bs[k][64 + tx * 4];
        float a[8] = {a0.x, a0.y, a0.z, a0.w, a1.x, a1.y, a1.z, a1.w};
        float b[8] = {b0.x, b0.y, b0.z, b0.w, b1.x, b1.y, b1.z, b1.w};
        #pragma unroll
        for (int i = 0; i < 8; i++)
            #pragma unroll
            for (int j = 0; j < 8; j++)
                acc[i][j] += a[i] * b[j];
    }
}

// ---------------- proj & values GEMMs (double-buffered, 1 sync/step) ----------------
__global__ __launch_bounds__(256) void k_img(const float* __restrict__ img,
                                             const float* __restrict__ sim,
                                             const float* __restrict__ vw) {
    __shared__ float As[2][8][132];
    __shared__ float Bs[2][8][128];
    int z = blockIdx.z, b = z >> 1, sel = z & 1;
    int n0 = blockIdx.x * 128, m0 = blockIdx.y * 128;
    const float* Ab = img + (size_t)b * CVAL * HW;
    int t = threadIdx.x, tx = t & 15, ty = t >> 4;
    int kr = t >> 5, q4 = (t & 31) * 4;
    int bn = t >> 1, bkq = (t & 1) * 4;
    float acc[8][8] = {};

    // prologue: stage 0
    {
        float4 av = *(const float4*)&Ab[(size_t)kr * HW + m0 + q4];
        float4 bv;
        if (sel == 0) bv = *(const float4*)&sim[(size_t)kr * CVAL + n0 + q4];
        else          bv = *(const float4*)&vw[(size_t)(n0 + bn) * CVAL + bkq];
        *(float4*)&As[0][kr][q4] = av;
        if (sel == 0) {
            *(float4*)&Bs[0][kr][q4] = bv;
        } else {
            Bs[0][bkq + 0][bn] = bv.x; Bs[0][bkq + 1][bn] = bv.y;
            Bs[0][bkq + 2][bn] = bv.z; Bs[0][bkq + 3][bn] = bv.w;
        }
    }
    __syncthreads();

    #pragma unroll 1
    for (int k0 = 0; k0 < CVAL; k0 += 8) {
        int cur = (k0 >> 3) & 1;
        float4 av, bv;
        bool more = (k0 + 8 < CVAL);
        if (more) {
            av = *(const float4*)&Ab[(size_t)(k0 + 8 + kr) * HW + m0 + q4];
            if (sel == 0) bv = *(const float4*)&sim[(size_t)(k0 + 8 + kr) * CVAL + n0 + q4];
            else          bv = *(const float4*)&vw[(size_t)(n0 + bn) * CVAL + k0 + 8 + bkq];
        }
        gemm_tile_compute(As[cur], Bs[cur], acc, tx, ty);
        if (more) {
            int nxt = cur ^ 1;
            *(float4*)&As[nxt][kr][q4] = av;
            if (sel == 0) {
                *(float4*)&Bs[nxt][kr][q4] = bv;
            } else {
                Bs[nxt][bkq + 0][bn] = bv.x; Bs[nxt][bkq + 1][bn] = bv.y;
                Bs[nxt][bkq + 2][bn] = bv.z; Bs[nxt][bkq + 3][bn] = bv.w;
            }
        }
        __syncthreads();
    }

    float* C = sel ? (g_values + (size_t)b * NTOK * CVAL) : (g_proj + (size_t)b * HW * CVAL);
    __nv_bfloat16* Ch = g_projh + (size_t)b * HW * CVAL;
    #pragma unroll
    for (int im = 0; im < 2; im++)
        #pragma unroll
        for (int i = 0; i < 4; i++) {
            size_t m = (size_t)m0 + im * 64 + ty * 4 + i;
            #pragma unroll
            for (int in = 0; in < 2; in++) {
                float4 o = make_float4(acc[im * 4 + i][in * 4 + 0], acc[im * 4 + i][in * 4 + 1],
                                       acc[im * 4 + i][in * 4 + 2], acc[im * 4 + i][in * 4 + 3]);
                size_t off = m * CVAL + n0 + in * 64 + tx * 4;
                *(float4*)&C[off] = o;
                if (sel == 0) {
                    __nv_bfloat162 p0 = __floats2bfloat162_rn(o.x, o.y);
                    __nv_bfloat162 p1 = __floats2bfloat162_rn(o.z, o.w);
                    *(__nv_bfloat162*)&Ch[off]     = p0;
                    *(__nv_bfloat162*)&Ch[off + 2] = p1;
                }
            }
        }
}

// ---------------- values last row (exe): warp-per-output, coalesced ----------------
__global__ __launch_bounds__(256) void k_vexe(const float* __restrict__ exe,
                                              const float* __restrict__ vw) {
    __shared__ float ex[256];
    int b = blockIdx.x, t = threadIdx.x;
    int warp = t >> 5, lane = t & 31;
    ex[t] = 1.2f * exe[b * 256 + t];
    __syncthreads();
    #pragma unroll
    for (int dd = 0; dd < 32; dd++) {
        int d = warp * 32 + dd;
        float part = 0.f;
        #pragma unroll
        for (int c8 = 0; c8 < 8; c8++) {
            int c = lane + c8 * 32;
            part += ex[c] * vw[d * 256 + c];
        }
        #pragma unroll
        for (int o = 16; o; o >>= 1) part += __shfl_xor_sync(0xffffffffu, part, o);
        if (lane == 0) g_values[((size_t)b * NTOK + HW) * CVAL + d] = part;
    }
}

// ---------------- exact fp32 exe column (for top-k) ----------------
__global__ __launch_bounds__(256) void k_execol(const float* __restrict__ exe) {
    int warp = threadIdx.x >> 5, lane = threadIdx.x & 31;
    int b = blockIdx.y;
    int m = blockIdx.x * 8 + warp;
    const float* pr = g_proj + ((size_t)b * HW + m) * CVAL;
    const float* ex = exe + b * CVAL;
    float part = 0.f;
    #pragma unroll
    for (int c = 0; c < 8; c++) {
        int cc = lane + c * 32;
        part += pr[cc] * ex[cc];
    }
    #pragma unroll
    for (int o = 16; o; o >>= 1) part += __shfl_xor_sync(0xffffffffu, part, o);
    if (lane == 0) g_attn_exe[(size_t)b * HW + m] = 1.2f * part;
}

// ---------------- attn GEMM (bf16 wmma, 64x256 tile, 4 warps x 64x64, 2 CTAs/SM) --------
#define A_LD 40            // 64 x 40 bf16 = 5120 B per stage
#define B_LD 264           // 32 x 264 bf16 = 16896 B per stage
#define ASZ  (64 * A_LD * 2)
#define BSZ  (32 * B_LD * 2)
#define STG  (ASZ + BSZ)                  // 22016 B
#define ATTN_SMEM (3 * STG)               // 66048 B -> 2 CTAs/SM
#define FRAG_LD 24

__global__ __launch_bounds__(128, 2) void k_attn() {
    extern __shared__ __align__(16) char sm[];
    int b = blockIdx.z, bx = blockIdx.x;
    int n0 = bx * 256, m0 = blockIdx.y * 64;
    const __nv_bfloat16* A  = g_projh   + (size_t)b * HW * CVAL;
    const __nv_bfloat16* Bm = g_concath + (size_t)b * CVAL * NPAD;
    int t = threadIdx.x, w = t >> 5, lane = t & 31;   // warp w owns n-slice w*64

    wmma::fragment<wmma::accumulator, 16, 16, 16, float> acc[4][4];
    #pragma unroll
    for (int i = 0; i < 4; i++)
        #pragma unroll
        for (int j = 0; j < 4; j++)
            wmma::fill_fragment(acc[i][j], 0.0f);

    #define ISSUE(ST, K0) do {                                                          \
        __nv_bfloat16* As_ = (__nv_bfloat16*)(sm + (ST) * STG);                         \
        __nv_bfloat16* Bs_ = (__nv_bfloat16*)(sm + (ST) * STG + ASZ);                   \
        _Pragma("unroll")                                                               \
        for (int i_ = 0; i_ < 2; i_++) {                                                \
            int s_ = t + i_ * 128;                                                      \
            int r_ = s_ >> 2, c_ = s_ & 3;                                              \
            cpa16(As_ + r_ * A_LD + c_ * 8, &A[(size_t)(m0 + r_) * CVAL + (K0) + c_ * 8]); } \
        _Pragma("unroll")                                                               \
        for (int i_ = 0; i_ < 8; i_++) {                                                \
            int s_ = t + i_ * 128;                                                      \
            int r_ = s_ >> 5, c_ = s_ & 31;                                             \
            cpa16(Bs_ + r_ * B_LD + c_ * 8, &Bm[(size_t)((K0) + r_) * NPAD + n0 + c_ * 8]); } \
        asm volatile("cp.async.commit_group;\n" ::: "memory");                          \
    } while (0)

    ISSUE(0, 0);
    ISSUE(1, 32);
    #pragma unroll
    for (int ks = 0; ks < 8; ks++) {
        int st = ks % 3;
        if (ks < 7) asm volatile("cp.async.wait_group 1;\n" ::: "memory");
        else        asm volatile("cp.async.wait_group 0;\n" ::: "memory");
        __syncthreads();
        if (ks < 6) ISSUE((ks + 2) % 3, (ks + 2) * 32);
        const __nv_bfloat16* As_ = (const __nv_bfloat16*)(sm + st * STG);
        const __nv_bfloat16* Bs_ = (const __nv_bfloat16*)(sm + st * STG + ASZ);
        #pragma unroll
        for (int kk = 0; kk < 2; kk++) {
            wmma::fragment<wmma::matrix_a, 16, 16, 16, __nv_bfloat16, wmma::row_major> af[4];
            wmma::fragment<wmma::matrix_b, 16, 16, 16, __nv_bfloat16, wmma::row_major> bf[4];
            #pragma unroll
            for (int i = 0; i < 4; i++)
                wmma::load_matrix_sync(af[i], As_ + (i * 16) * A_LD + kk * 16, A_LD);
            #pragma unroll
            for (int j = 0; j < 4; j++)
                wmma::load_matrix_sync(bf[j], Bs_ + (kk * 16) * B_LD + w * 64 + j * 16, B_LD);
            #pragma unroll
            for (int i = 0; i < 4; i++)
                #pragma unroll
                for (int j = 0; j < 4; j++)
                    wmma::mma_sync(acc[i][j], af[i], bf[j], acc[i][j]);
        }
    }

    // -------- epilogue: bf16 store + per-tile row max (reuses stage smem) --------
    __syncthreads();
    float* fragbuf = (float*)sm + w * (16 * FRAG_LD);              // 4 warps x 1536 B
    float* rowmaxp = (float*)(sm + 4 * 16 * FRAG_LD * 4);          // [64][4]
    int lr = lane & 15, lh = lane >> 4;
    bool lastT = (bx == NTILES - 1);
    #pragma unroll
    for (int i = 0; i < 4; i++) {
        int mloc = i * 16 + lr;
        size_t grow = ((size_t)b * HW + m0 + mloc) * NPAD;
        float mj = -INFINITY;
        #pragma unroll
        for (int j = 0; j < 4; j++) {
            wmma::store_matrix_sync(fragbuf, acc[i][j], FRAG_LD, wmma::mem_row_major);
            __syncwarp();
            const float* fr = fragbuf + lr * FRAG_LD + lh * 8;
            int gc = n0 + w * 64 + j * 16 + lh * 8;
            float vv[8];
            #pragma unroll
            for (int e = 0; e < 8; e++) {
                float v = fr[e];
                if (lastT && (gc + e) > HW) v = -INFINITY;
                mj = fmaxf(mj, v);
                vv[e] = v;
            }
            unsigned u[4];
            #pragma unroll
            for (int p = 0; p < 4; p++) {
                __nv_bfloat162 bp = __floats2bfloat162_rn(vv[2 * p], vv[2 * p + 1]);
                u[p] = *(unsigned*)&bp;
            }
            *(uint4*)(g_attnh + grow + gc) = make_uint4(u[0], u[1], u[2], u[3]);
            __syncwarp();
        }
        float omx = __shfl_xor_sync(0xffffffffu, mj, 16);
        mj = fmaxf(mj, omx);
        if (lh == 0) rowmaxp[mloc * 4 + w] = mj;
    }
    __syncthreads();
    if (t < 64) {
        float m4 = fmaxf(fmaxf(rowmaxp[t * 4 + 0], rowmaxp[t * 4 + 1]),
                         fmaxf(rowmaxp[t * 4 + 2], rowmaxp[t * 4 + 3]));
        g_tilemax[((size_t)b * HW + m0 + t) * NTILES + bx] = m4;
    }
}

// ---------------- top-k (exact, jax tie rule) + query gather, 1024 threads ----------------
__global__ __launch_bounds__(1024) void k_topk(float* __restrict__ out) {
    __shared__ float sv[HW];
    __shared__ int   qids[TOPKN];
    __shared__ float rv[32];
    __shared__ int   ri[32];
    int b = blockIdx.x, t = threadIdx.x;
    int warp = t >> 5, lane = t & 31;
    for (int i = t; i < HW; i += 1024)
        sv[i] = g_attn_exe[(size_t)b * HW + i];
    __syncthreads();
    for (int j = 0; j < TOPKN; j++) {
        float bv = -3.4e38f; int bi = 1 << 30;
        #pragma unroll
        for (int q = 0; q < 4; q++) {
            int i = t + q * 1024;
            float v = sv[i];
            if (v > bv || (v == bv && i < bi)) { bv = v; bi = i; }
        }
        #pragma unroll
        for (int o = 16; o; o >>= 1) {
            float ov = __shfl_down_sync(0xffffffffu, bv, o);
            int   oi = __shfl_down_sync(0xffffffffu, bi, o);
            if (ov > bv || (ov == bv && oi < bi)) { bv = ov; bi = oi; }
        }
        if (lane == 0) { rv[warp] = bv; ri[warp] = bi; }
        __syncthreads();
        if (warp == 0) {
            float fv = rv[lane]; int fi = ri[lane];
            #pragma unroll
            for (int o = 16; o; o >>= 1) {
                float ov = __shfl_down_sync(0xffffffffu, fv, o);
                int   oi = __shfl_down_sync(0xffffffffu, fi, o);
                if (ov > fv || (ov == fv && oi < fi)) { fv = ov; fi = oi; }
            }
            if (lane == 0) {
                qids[j] = fi;
                sv[fi] = -3.4e38f;
            }
        }
        __syncthreads();
    }
    for (int idx = t; idx < TOPKN * 256; idx += 1024) {
        int j = idx >> 8, d = idx & 255;
        out[QOFF + ((size_t)(b * TOPKN + j)) * 256 + d] =
            g_values[((size_t)b * NTOK + qids[j]) * 256 + d];
    }
}

// ---------------- fused softmax + sparse PV (tile-skip, exact recompute) --------
__global__ __launch_bounds__(256) void k_smpv(float* __restrict__ out) {
    int warp = threadIdx.x >> 5, lane = threadIdx.x & 31;
    size_t row = (size_t)blockIdx.x * 8 + warp;      // b*4096+m
    int b = (int)(row >> 12);

    // per-tile row maxes -> global row max
    const float* tm = g_tilemax + row * NTILES;
    float mxl = (lane < NTILES) ? tm[lane] : -INFINITY;
    float mx = mxl;
    #pragma unroll
    for (int o = 16; o; o >>= 1) mx = fmaxf(mx, __shfl_xor_sync(0xffffffffu, mx, o));
    float thr = mx - 46.0f;

    float4 o0 = make_float4(0.f, 0.f, 0.f, 0.f);
    float4 o1 = make_float4(0.f, 0.f, 0.f, 0.f);
    float sum = 0.f;   // warp-uniform
    const float* Vb = g_values  + (size_t)b * NTOK * CVAL;
    const float* pr = g_proj    + row * CVAL;
    const float* cT = g_concatT + (size_t)b * NPAD * CVAL;
    const uint4* rp = (const uint4*)(g_attnh + row * NPAD);   // 544 uint4 (8 bf16 each)

    #pragma unroll 1
    for (int i = 0; i < NTILES; i++) {
        float tmax = __shfl_sync(0xffffffffu, mxl, i);
        if (tmax <= thr) continue;                 // exact skip: all entries <= tile max
        uint4 u = rp[i * 32 + lane];
        float2 f0 = __bfloat1622float2(*(__nv_bfloat162*)&u.x);
        float2 f1 = __bfloat1622float2(*(__nv_bfloat162*)&u.y);
        float2 f2 = __bfloat1622float2(*(__nv_bfloat162*)&u.z);
        float2 f3 = __bfloat1622float2(*(__nv_bfloat162*)&u.w);
        bool pred = (f0.x > thr) | (f0.y > thr) | (f1.x > thr) | (f1.y > thr) |
                    (f2.x > thr) | (f2.y > thr) | (f3.x > thr) | (f3.y > thr);
        unsigned bal = __ballot_sync(0xffffffffu, pred);
        while (bal) {
            int src = __ffs(bal) - 1;
            bal &= bal - 1;
            unsigned su[4];
            su[0] = __shfl_sync(0xffffffffu, u.x, src);
            su[1] = __shfl_sync(0xffffffffu, u.y, src);
            su[2] = __shfl_sync(0xffffffffu, u.z, src);
            su[3] = __shfl_sync(0xffffffffu, u.w, src);
            int nb = (i * 32 + src) * 8;
            #pragma unroll
            for (int p = 0; p < 4; p++) {
                float2 fp = __bfloat1622float2(*(__nv_bfloat162*)&su[p]);
                float sv2[2] = {fp.x, fp.y};
                #pragma unroll
                for (int e = 0; e < 2; e++) {
                    if (sv2[e] > thr) {
                        int n = nb + p * 2 + e;
                        // exact fp32 logit: cooperative dot(proj_row, concatT_row)
                        const float* cn = cT + (size_t)n * CVAL;
                        float part = 0.f;
                        #pragma unroll
                        for (int cc = 0; cc < 8; cc++) {
                            int k = lane + cc * 32;
                            part += pr[k] * cn[k];
                        }
                        #pragma unroll
                        for (int o = 16; o; o >>= 1)
                            part += __shfl_xor_sync(0xffffffffu, part, o);
                        float pw = __expf(part - mx);
                        sum += pw;
                        const float4* Vr = (const float4*)(Vb + (size_t)n * CVAL);
                        float4 v0 = Vr[lane * 2], v1 = Vr[lane * 2 + 1];
                        o0.x += pw * v0.x; o0.y += pw * v0.y; o0.z += pw * v0.z; o0.w += pw * v0.w;
                        o1.x += pw * v1.x; o1.y += pw * v1.y; o1.z += pw * v1.z; o1.w += pw * v1.w;
                    }
                }
            }
        }
    }
    float inv = 1.0f / sum;
    o0.x *= inv; o0.y *= inv; o0.z *= inv; o0.w *= inv;
    o1.x *= inv; o1.y *= inv; o1.z *= inv; o1.w *= inv;
    float4* op = (float4*)(out + row * CVAL);
    op[lane * 2] = o0;
    op[lane * 2 + 1] = o1;
}

// ---------------- launch ----------------
extern "C" void kernel_launch(void* const* d_in, const int* in_sizes, int n_in,
                              void* d_out, int out_size) {
    const float* img = (const float*)d_in[0];
    const float* exe = (const float*)d_in[1];
    const float* sim = (const float*)d_in[2];
    const float* vw  = (const float*)d_in[3];
    float* out = (float*)d_out;

    cudaFuncSetAttribute(k_attn, cudaFuncAttributeMaxDynamicSharedMemorySize, ATTN_SMEM);

    k_concat2<<<dim3(NPAD / 32, CVAL / 32, BVAL), 256>>>(img, exe);   // 0
    k_img<<<dim3(2, 32, 16), 256>>>(img, sim, vw);                    // 1: proj+values
    k_vexe<<<8, 256>>>(exe, vw);                                      // 2: values[4096]
    k_attn<<<dim3(NTILES, 64, 8), 128, ATTN_SMEM>>>();                // 3: PROFILED SLOT
    k_execol<<<dim3(512, 8), 256>>>(exe);                             // 4: exact exe col
    k_topk<<<8, 1024>>>(out);                                         // 5: top-150 + gather
    k_smpv<<<4096, 256>>>(out);                                       // 6: softmax + PV
}

// round 13
// speedup vs baseline: 1.1918x; 1.1918x over previous
#include <cuda_runtime.h>
#include <cuda_fp16.h>
#include <mma.h>
#include <cstdint>

using namespace nvcuda;

#define BVAL 8
#define CVAL 256
#define HW   4096
#define NTOK 4097
#define NPAD 4352          // 17 tiles of 256
#define NTILES 17
#define TOPKN 150
#define QOFF ((size_t)BVAL*HW*CVAL)   // offset of queries in d_out

// ---------------- scratch (static device globals; no allocation) ----------------
__device__ __align__(256) __half g_concath[(size_t)BVAL*CVAL*NPAD];   // concat fp16 [c][n]
__device__ __align__(256) float g_concatT [(size_t)BVAL*NPAD*CVAL];   // concat^T fp32 [n][c]
__device__ __align__(256) float g_proj  [(size_t)BVAL*HW*CVAL];       // proj fp32
__device__ __align__(256) __half g_projh[(size_t)BVAL*HW*CVAL];       // proj fp16
__device__ __align__(256) float g_values[(size_t)BVAL*NTOK*CVAL];     // values fp32
__device__ __align__(256) __half g_attnh[(size_t)BVAL*HW*NPAD];       // logits fp16
__device__ __align__(256) float g_tilemax[(size_t)BVAL*HW*NTILES];    // per-tile row max
__device__ __align__(256) float g_attn_exe[(size_t)BVAL*HW];          // exact fp32 exe column

// ---------------- cp.async helper ----------------
__device__ __forceinline__ void cpa16(void* dst, const void* src) {
    unsigned d = (unsigned)__cvta_generic_to_shared(dst);
    asm volatile("cp.async.cg.shared.global [%0], [%1], 16;\n" :: "r"(d), "l"(src));
}

// ---------------- merged concat: fp16 [c][n] + fp32 transpose [n][c], img read once ------
__global__ __launch_bounds__(256) void k_concat2(const float* __restrict__ img,
                                                 const float* __restrict__ exe) {
    __shared__ float tile[32][33];
    int b = blockIdx.z;
    int n0 = blockIdx.x * 32, c0 = blockIdx.y * 32;
    int tx = threadIdx.x & 31, ty = threadIdx.x >> 5;   // 32 x 8
    #pragma unroll
    for (int j = 0; j < 4; j++) {
        int c = c0 + ty + j * 8, n = n0 + tx;
        float v;
        if (n < HW) v = img[((size_t)b * CVAL + c) * HW + n];
        else        v = (n == HW) ? 1.2f * exe[b * CVAL + c] : 0.0f;
        tile[ty + j * 8][tx] = v;
        g_concath[((size_t)b * CVAL + c) * NPAD + n] = __float2half(v);
    }
    __syncthreads();
    #pragma unroll
    for (int j = 0; j < 4; j++) {
        int n = n0 + ty + j * 8, c = c0 + tx;
        g_concatT[((size_t)b * NPAD + n) * CVAL + c] = tile[tx][ty + j * 8];
    }
}

// ---------------- fp32 SIMT GEMM microkernel ----------------
__device__ __forceinline__ void gemm_tile_compute(const float (*As)[132], const float (*Bs)[128],
                                                  float (&acc)[8][8], int tx, int ty) {
    #pragma unroll
    for (int k = 0; k < 8; k++) {
        float4 a0 = *(const float4*)&As[k][ty * 4];
        float4 a1 = *(const float4*)&As[k][64 + ty * 4];
        float4 b0 = *(const float4*)&Bs[k][tx * 4];
        float4 b1 = *(const float4*)&Bs[k][64 + tx * 4];
        float a[8] = {a0.x, a0.y, a0.z, a0.w, a1.x, a1.y, a1.z, a1.w};
        float b[8] = {b0.x, b0.y, b0.z, b0.w, b1.x, b1.y, b1.z, b1.w};
        #pragma unroll
        for (int i = 0; i < 8; i++)
            #pragma unroll
            for (int j = 0; j < 8; j++)
                acc[i][j] += a[i] * b[j];
    }
}

// ---------------- proj & values GEMMs (double-buffered, 1 sync/step) ----------------
__global__ __launch_bounds__(256) void k_img(const float* __restrict__ img,
                                             const float* __restrict__ sim,
                                             const float* __restrict__ vw) {
    __shared__ float As[2][8][132];
    __shared__ float Bs[2][8][128];
    int z = blockIdx.z, b = z >> 1, sel = z & 1;
    int n0 = blockIdx.x * 128, m0 = blockIdx.y * 128;
    const float* Ab = img + (size_t)b * CVAL * HW;
    int t = threadIdx.x, tx = t & 15, ty = t >> 4;
    int kr = t >> 5, q4 = (t & 31) * 4;
    int bn = t >> 1, bkq = (t & 1) * 4;
    float acc[8][8] = {};

    // prologue: stage 0
    {
        float4 av = *(const float4*)&Ab[(size_t)kr * HW + m0 + q4];
        float4 bv;
        if (sel == 0) bv = *(const float4*)&sim[(size_t)kr * CVAL + n0 + q4];
        else          bv = *(const float4*)&vw[(size_t)(n0 + bn) * CVAL + bkq];
        *(float4*)&As[0][kr][q4] = av;
        if (sel == 0) {
            *(float4*)&Bs[0][kr][q4] = bv;
        } else {
            Bs[0][bkq + 0][bn] = bv.x; Bs[0][bkq + 1][bn] = bv.y;
            Bs[0][bkq + 2][bn] = bv.z; Bs[0][bkq + 3][bn] = bv.w;
        }
    }
    __syncthreads();

    #pragma unroll 1
    for (int k0 = 0; k0 < CVAL; k0 += 8) {
        int cur = (k0 >> 3) & 1;
        float4 av, bv;
        bool more = (k0 + 8 < CVAL);
        if (more) {
            av = *(const float4*)&Ab[(size_t)(k0 + 8 + kr) * HW + m0 + q4];
            if (sel == 0) bv = *(const float4*)&sim[(size_t)(k0 + 8 + kr) * CVAL + n0 + q4];
            else          bv = *(const float4*)&vw[(size_t)(n0 + bn) * CVAL + k0 + 8 + bkq];
        }
        gemm_tile_compute(As[cur], Bs[cur], acc, tx, ty);
        if (more) {
            int nxt = cur ^ 1;
            *(float4*)&As[nxt][kr][q4] = av;
            if (sel == 0) {
                *(float4*)&Bs[nxt][kr][q4] = bv;
            } else {
                Bs[nxt][bkq + 0][bn] = bv.x; Bs[nxt][bkq + 1][bn] = bv.y;
                Bs[nxt][bkq + 2][bn] = bv.z; Bs[nxt][bkq + 3][bn] = bv.w;
            }
        }
        __syncthreads();
    }

    float* C = sel ? (g_values + (size_t)b * NTOK * CVAL) : (g_proj + (size_t)b * HW * CVAL);
    __half* Ch = g_projh + (size_t)b * HW * CVAL;
    #pragma unroll
    for (int im = 0; im < 2; im++)
        #pragma unroll
        for (int i = 0; i < 4; i++) {
            size_t m = (size_t)m0 + im * 64 + ty * 4 + i;
            #pragma unroll
            for (int in = 0; in < 2; in++) {
                float4 o = make_float4(acc[im * 4 + i][in * 4 + 0], acc[im * 4 + i][in * 4 + 1],
                                       acc[im * 4 + i][in * 4 + 2], acc[im * 4 + i][in * 4 + 3]);
                size_t off = m * CVAL + n0 + in * 64 + tx * 4;
                *(float4*)&C[off] = o;
                if (sel == 0) {
                    __half2 p0 = __floats2half2_rn(o.x, o.y);
                    __half2 p1 = __floats2half2_rn(o.z, o.w);
                    *(__half2*)&Ch[off]     = p0;
                    *(__half2*)&Ch[off + 2] = p1;
                }
            }
        }
}

// ---------------- values last row (exe): warp-per-output, coalesced ----------------
__global__ __launch_bounds__(256) void k_vexe(const float* __restrict__ exe,
                                              const float* __restrict__ vw) {
    __shared__ float ex[256];
    int b = blockIdx.x, t = threadIdx.x;
    int warp = t >> 5, lane = t & 31;
    ex[t] = 1.2f * exe[b * 256 + t];
    __syncthreads();
    #pragma unroll
    for (int dd = 0; dd < 32; dd++) {
        int d = warp * 32 + dd;
        float part = 0.f;
        #pragma unroll
        for (int c8 = 0; c8 < 8; c8++) {
            int c = lane + c8 * 32;
            part += ex[c] * vw[d * 256 + c];
        }
        #pragma unroll
        for (int o = 16; o; o >>= 1) part += __shfl_xor_sync(0xffffffffu, part, o);
        if (lane == 0) g_values[((size_t)b * NTOK + HW) * CVAL + d] = part;
    }
}

// ---------------- exact fp32 exe column (for top-k) ----------------
__global__ __launch_bounds__(256) void k_execol(const float* __restrict__ exe) {
    int warp = threadIdx.x >> 5, lane = threadIdx.x & 31;
    int b = blockIdx.y;
    int m = blockIdx.x * 8 + warp;
    const float* pr = g_proj + ((size_t)b * HW + m) * CVAL;
    const float* ex = exe + b * CVAL;
    float part = 0.f;
    #pragma unroll
    for (int c = 0; c < 8; c++) {
        int cc = lane + c * 32;
        part += pr[cc] * ex[cc];
    }
    #pragma unroll
    for (int o = 16; o; o >>= 1) part += __shfl_xor_sync(0xffffffffu, part, o);
    if (lane == 0) g_attn_exe[(size_t)b * HW + m] = 1.2f * part;
}

// ---------------- attn GEMM (fp16 wmma + fp16 accum, 64x256 tile, 3 CTAs/SM) ------------
#define A_LD 40            // 64 x 40 half = 5120 B per stage
#define B_LD 264           // 32 x 264 half = 16896 B per stage
#define ASZ  (64 * A_LD * 2)
#define BSZ  (32 * B_LD * 2)
#define STG  (ASZ + BSZ)                  // 22016 B
#define ATTN_SMEM (3 * STG)               // 66048 B -> 3 CTAs/SM
#define FRAG_LD 32                        // half staging ld (64 B rows)

__global__ __launch_bounds__(128, 3) void k_attn() {
    extern __shared__ __align__(16) char sm[];
    int b = blockIdx.z, bx = blockIdx.x;
    int n0 = bx * 256, m0 = blockIdx.y * 64;
    const __half* A  = g_projh   + (size_t)b * HW * CVAL;
    const __half* Bm = g_concath + (size_t)b * CVAL * NPAD;
    int t = threadIdx.x, w = t >> 5, lane = t & 31;   // warp w owns n-slice w*64

    wmma::fragment<wmma::accumulator, 16, 16, 16, __half> acc[4][4];
    #pragma unroll
    for (int i = 0; i < 4; i++)
        #pragma unroll
        for (int j = 0; j < 4; j++)
            wmma::fill_fragment(acc[i][j], __float2half(0.0f));

    #define ISSUE(ST, K0) do {                                                          \
        __half* As_ = (__half*)(sm + (ST) * STG);                                       \
        __half* Bs_ = (__half*)(sm + (ST) * STG + ASZ);                                 \
        _Pragma("unroll")                                                               \
        for (int i_ = 0; i_ < 2; i_++) {                                                \
            int s_ = t + i_ * 128;                                                      \
            int r_ = s_ >> 2, c_ = s_ & 3;                                              \
            cpa16(As_ + r_ * A_LD + c_ * 8, &A[(size_t)(m0 + r_) * CVAL + (K0) + c_ * 8]); } \
        _Pragma("unroll")                                                               \
        for (int i_ = 0; i_ < 8; i_++) {                                                \
            int s_ = t + i_ * 128;                                                      \
            int r_ = s_ >> 5, c_ = s_ & 31;                                             \
            cpa16(Bs_ + r_ * B_LD + c_ * 8, &Bm[(size_t)((K0) + r_) * NPAD + n0 + c_ * 8]); } \
        asm volatile("cp.async.commit_group;\n" ::: "memory");                          \
    } while (0)

    ISSUE(0, 0);
    ISSUE(1, 32);
    #pragma unroll
    for (int ks = 0; ks < 8; ks++) {
        int st = ks % 3;
        if (ks < 7) asm volatile("cp.async.wait_group 1;\n" ::: "memory");
        else        asm volatile("cp.async.wait_group 0;\n" ::: "memory");
        __syncthreads();
        if (ks < 6) ISSUE((ks + 2) % 3, (ks + 2) * 32);
        const __half* As_ = (const __half*)(sm + st * STG);
        const __half* Bs_ = (const __half*)(sm + st * STG + ASZ);
        #pragma unroll
        for (int kk = 0; kk < 2; kk++) {
            wmma::fragment<wmma::matrix_a, 16, 16, 16, __half, wmma::row_major> af[4];
            wmma::fragment<wmma::matrix_b, 16, 16, 16, __half, wmma::row_major> bf[4];
            #pragma unroll
            for (int i = 0; i < 4; i++)
                wmma::load_matrix_sync(af[i], As_ + (i * 16) * A_LD + kk * 16, A_LD);
            #pragma unroll
            for (int j = 0; j < 4; j++)
                wmma::load_matrix_sync(bf[j], Bs_ + (kk * 16) * B_LD + w * 64 + j * 16, B_LD);
            #pragma unroll
            for (int i = 0; i < 4; i++)
                #pragma unroll
                for (int j = 0; j < 4; j++)
                    wmma::mma_sync(acc[i][j], af[i], bf[j], acc[i][j]);
        }
    }

    // -------- epilogue: fp16 store + per-tile row max (reuses stage smem) --------
    __syncthreads();
    __half* fragbuf = (__half*)sm + w * (16 * FRAG_LD);            // 4 warps x 1 KB
    float* rowmaxp = (float*)(sm + 4 * 16 * FRAG_LD * 2);          // [64][4]
    int lr = lane & 15, lh = lane >> 4;
    bool lastT = (bx == NTILES - 1);
    #pragma unroll
    for (int i = 0; i < 4; i++) {
        int mloc = i * 16 + lr;
        size_t grow = ((size_t)b * HW + m0 + mloc) * NPAD;
        float mj = -INFINITY;
        #pragma unroll
        for (int j = 0; j < 4; j++) {
            wmma::store_matrix_sync(fragbuf, acc[i][j], FRAG_LD, wmma::mem_row_major);
            __syncwarp();
            const __half* fr = fragbuf + lr * FRAG_LD + lh * 8;
            int gc = n0 + w * 64 + j * 16 + lh * 8;
            unsigned u[4];
            #pragma unroll
            for (int p = 0; p < 4; p++) {
                __half2 hp = *(const __half2*)(fr + p * 2);
                float2 f = __half22float2(hp);
                if (lastT) {
                    if (gc + p * 2     > HW) { f.x = -INFINITY; hp.x = __float2half(-INFINITY); }
                    if (gc + p * 2 + 1 > HW) { f.y = -INFINITY; hp.y = __float2half(-INFINITY); }
                }
                mj = fmaxf(mj, fmaxf(f.x, f.y));
                u[p] = *(unsigned*)&hp;
            }
            *(uint4*)(g_attnh + grow + gc) = make_uint4(u[0], u[1], u[2], u[3]);
            __syncwarp();
        }
        float omx = __shfl_xor_sync(0xffffffffu, mj, 16);
        mj = fmaxf(mj, omx);
        if (lh == 0) rowmaxp[mloc * 4 + w] = mj;
    }
    __syncthreads();
    if (t < 64) {
        float m4 = fmaxf(fmaxf(rowmaxp[t * 4 + 0], rowmaxp[t * 4 + 1]),
                         fmaxf(rowmaxp[t * 4 + 2], rowmaxp[t * 4 + 3]));
        g_tilemax[((size_t)b * HW + m0 + t) * NTILES + bx] = m4;
    }
}

// ---------------- top-k (exact, jax tie rule) + query gather, 1024 threads ----------------
__global__ __launch_bounds__(1024) void k_topk(float* __restrict__ out) {
    __shared__ float sv[HW];
    __shared__ int   qids[TOPKN];
    __shared__ float rv[32];
    __shared__ int   ri[32];
    int b = blockIdx.x, t = threadIdx.x;
    int warp = t >> 5, lane = t & 31;
    for (int i = t; i < HW; i += 1024)
        sv[i] = g_attn_exe[(size_t)b * HW + i];
    __syncthreads();
    for (int j = 0; j < TOPKN; j++) {
        float bv = -3.4e38f; int bi = 1 << 30;
        #pragma unroll
        for (int q = 0; q < 4; q++) {
            int i = t + q * 1024;
            float v = sv[i];
            if (v > bv || (v == bv && i < bi)) { bv = v; bi = i; }
        }
        #pragma unroll
        for (int o = 16; o; o >>= 1) {
            float ov = __shfl_down_sync(0xffffffffu, bv, o);
            int   oi = __shfl_down_sync(0xffffffffu, bi, o);
            if (ov > bv || (ov == bv && oi < bi)) { bv = ov; bi = oi; }
        }
        if (lane == 0) { rv[warp] = bv; ri[warp] = bi; }
        __syncthreads();
        if (warp == 0) {
            float fv = rv[lane]; int fi = ri[lane];
            #pragma unroll
            for (int o = 16; o; o >>= 1) {
                float ov = __shfl_down_sync(0xffffffffu, fv, o);
                int   oi = __shfl_down_sync(0xffffffffu, fi, o);
                if (ov > fv || (ov == fv && oi < fi)) { fv = ov; fi = oi; }
            }
            if (lane == 0) {
                qids[j] = fi;
                sv[fi] = -3.4e38f;
            }
        }
        __syncthreads();
    }
    for (int idx = t; idx < TOPKN * 256; idx += 1024) {
        int j = idx >> 8, d = idx & 255;
        out[QOFF + ((size_t)(b * TOPKN + j)) * 256 + d] =
            g_values[((size_t)b * NTOK + qids[j]) * 256 + d];
    }
}

// ---------------- fused softmax + sparse PV (tile-skip, exact recompute) --------
__global__ __launch_bounds__(256) void k_smpv(float* __restrict__ out) {
    int warp = threadIdx.x >> 5, lane = threadIdx.x & 31;
    size_t row = (size_t)blockIdx.x * 8 + warp;      // b*4096+m
    int b = (int)(row >> 12);

    // per-tile row maxes -> global row max
    const float* tm = g_tilemax + row * NTILES;
    float mxl = (lane < NTILES) ? tm[lane] : -INFINITY;
    float mx = mxl;
    #pragma unroll
    for (int o = 16; o; o >>= 1) mx = fmaxf(mx, __shfl_xor_sync(0xffffffffu, mx, o));
    float thr = mx - 46.0f;

    float4 o0 = make_float4(0.f, 0.f, 0.f, 0.f);
    float4 o1 = make_float4(0.f, 0.f, 0.f, 0.f);
    float sum = 0.f;   // warp-uniform
    const float* Vb = g_values  + (size_t)b * NTOK * CVAL;
    const float* pr = g_proj    + row * CVAL;
    const float* cT = g_concatT + (size_t)b * NPAD * CVAL;
    const uint4* rp = (const uint4*)(g_attnh + row * NPAD);   // 544 uint4 (8 half each)

    #pragma unroll 1
    for (int i = 0; i < NTILES; i++) {
        float tmax = __shfl_sync(0xffffffffu, mxl, i);
        if (tmax <= thr) continue;                 // exact skip: all entries <= tile max
        uint4 u = rp[i * 32 + lane];
        float2 f0 = __half22float2(*(__half2*)&u.x);
        float2 f1 = __half22float2(*(__half2*)&u.y);
        float2 f2 = __half22float2(*(__half2*)&u.z);
        float2 f3 = __half22float2(*(__half2*)&u.w);
        bool pred = (f0.x > thr) | (f0.y > thr) | (f1.x > thr) | (f1.y > thr) |
                    (f2.x > thr) | (f2.y > thr) | (f3.x > thr) | (f3.y > thr);
        unsigned bal = __ballot_sync(0xffffffffu, pred);
        while (bal) {
            int src = __ffs(bal) - 1;
            bal &= bal - 1;
            unsigned su[4];
            su[0] = __shfl_sync(0xffffffffu, u.x, src);
            su[1] = __shfl_sync(0xffffffffu, u.y, src);
            su[2] = __shfl_sync(0xffffffffu, u.z, src);
            su[3] = __shfl_sync(0xffffffffu, u.w, src);
            int nb = (i * 32 + src) * 8;
            #pragma unroll
            for (int p = 0; p < 4; p++) {
                float2 fp = __half22float2(*(__half2*)&su[p]);
                float sv2[2] = {fp.x, fp.y};
                #pragma unroll
                for (int e = 0; e < 2; e++) {
                    if (sv2[e] > thr) {
                        int n = nb + p * 2 + e;
                        // exact fp32 logit: cooperative dot(proj_row, concatT_row)
                        const float* cn = cT + (size_t)n * CVAL;
                        float part = 0.f;
                        #pragma unroll
                        for (int cc = 0; cc < 8; cc++) {
                            int k = lane + cc * 32;
                            part += pr[k] * cn[k];
                        }
                        #pragma unroll
                        for (int o = 16; o; o >>= 1)
                            part += __shfl_xor_sync(0xffffffffu, part, o);
                        float pw = __expf(part - mx);
                        sum += pw;
                        const float4* Vr = (const float4*)(Vb + (size_t)n * CVAL);
                        float4 v0 = Vr[lane * 2], v1 = Vr[lane * 2 + 1];
                        o0.x += pw * v0.x; o0.y += pw * v0.y; o0.z += pw * v0.z; o0.w += pw * v0.w;
                        o1.x += pw * v1.x; o1.y += pw * v1.y; o1.z += pw * v1.z; o1.w += pw * v1.w;
                    }
                }
            }
        }
    }
    float inv = 1.0f / sum;
    o0.x *= inv; o0.y *= inv; o0.z *= inv; o0.w *= inv;
    o1.x *= inv; o1.y *= inv; o1.z *= inv; o1.w *= inv;
    float4* op = (float4*)(out + row * CVAL);
    op[lane * 2] = o0;
    op[lane * 2 + 1] = o1;
}

// ---------------- launch ----------------
extern "C" void kernel_launch(void* const* d_in, const int* in_sizes, int n_in,
                              void* d_out, int out_size) {
    const float* img = (const float*)d_in[0];
    const float* exe = (const float*)d_in[1];
    const float* sim = (const float*)d_in[2];
    const float* vw  = (const float*)d_in[3];
    float* out = (float*)d_out;

    cudaFuncSetAttribute(k_attn, cudaFuncAttributeMaxDynamicSharedMemorySize, ATTN_SMEM);

    k_concat2<<<dim3(NPAD / 32, CVAL / 32, BVAL), 256>>>(img, exe);   // 0
    k_img<<<dim3(2, 32, 16), 256>>>(img, sim, vw);                    // 1: proj+values
    k_vexe<<<8, 256>>>(exe, vw);                                      // 2: values[4096]
    k_attn<<<dim3(NTILES, 64, 8), 128, ATTN_SMEM>>>();                // 3: PROFILED SLOT
    k_execol<<<dim3(512, 8), 256>>>(exe);                             // 4: exact exe col
    k_topk<<<8, 1024>>>(out);                                         // 5: top-150 + gather
    k_smpv<<<4096, 256>>>(out);                                       // 6: softmax + PV
}

// round 14
// speedup vs baseline: 1.3951x; 1.1705x over previous
#include <cuda_runtime.h>
#include <cuda_fp16.h>
#include <mma.h>
#include <cstdint>

using namespace nvcuda;

#define BVAL 8
#define CVAL 256
#define HW   4096
#define NTOK 4097
#define NPAD 4352          // 17 tiles of 256
#define NTILES 17
#define TOPKN 150
#define QOFF ((size_t)BVAL*HW*CVAL)   // offset of queries in d_out
#define NB   512           // fused B cols: [sim | vw^T]

// ---------------- scratch (static device globals; no allocation) ----------------
__device__ __align__(256) __half g_concath[(size_t)BVAL*CVAL*NPAD];   // concat fp16 [c][n]
__device__ __align__(256) float  g_concatT [(size_t)BVAL*NPAD*CVAL];  // concat^T fp32 [n][c]
__device__ __align__(256) __half g_concatTh[(size_t)BVAL*NPAD*CVAL];  // concat^T hi fp16
__device__ __align__(256) __half g_concatTl[(size_t)BVAL*NPAD*CVAL];  // concat^T lo fp16
__device__ __align__(256) __half g_Bh[(size_t)CVAL*NB];               // [k][j] hi: sim | vw^T
__device__ __align__(256) __half g_Bl[(size_t)CVAL*NB];               // [k][j] lo
__device__ __align__(256) float  g_proj  [(size_t)BVAL*HW*CVAL];      // proj fp32
__device__ __align__(256) __half g_projh[(size_t)BVAL*HW*CVAL];       // proj fp16
__device__ __align__(256) float  g_values[(size_t)BVAL*NTOK*CVAL];    // values fp32
__device__ __align__(256) __half g_attnh[(size_t)BVAL*HW*NPAD];       // logits fp16
__device__ __align__(256) float  g_tilemax[(size_t)BVAL*HW*NTILES];   // per-tile row max
__device__ __align__(256) float  g_attn_exe[(size_t)BVAL*HW];         // exact fp32 exe column

// ---------------- cp.async helper ----------------
__device__ __forceinline__ void cpa16(void* dst, const void* src) {
    unsigned d = (unsigned)__cvta_generic_to_shared(dst);
    asm volatile("cp.async.cg.shared.global [%0], [%1], 16;\n" :: "r"(d), "l"(src));
}

// ---------------- concat fp16 [c][n] (attn B operand) ----------------
__global__ void k_concatH(const float* __restrict__ img, const float* __restrict__ exe) {
    size_t idx = (size_t)blockIdx.x * blockDim.x + threadIdx.x;   // float4 group index
    size_t total = (size_t)BVAL * CVAL * (NPAD / 4);
    if (idx >= total) return;
    size_t n4 = idx % (NPAD / 4);
    size_t bc = idx / (NPAD / 4);
    float4 v;
    if (n4 < HW / 4) {
        v = ((const float4*)img)[bc * (HW / 4) + n4];
    } else {
        int n = (int)n4 * 4;
        float t[4];
        #pragma unroll
        for (int e = 0; e < 4; e++) {
            int nn = n + e;
            t[e] = (nn == HW) ? 1.2f * exe[bc] : 0.0f;
        }
        v = make_float4(t[0], t[1], t[2], t[3]);
    }
    __half2 p0 = __floats2half2_rn(v.x, v.y);
    __half2 p1 = __floats2half2_rn(v.z, v.w);
    ((__half2*)g_concath)[idx * 2]     = p0;
    ((__half2*)g_concath)[idx * 2 + 1] = p1;
}

// ---------------- concat^T: fp32 [n][c] + hi/lo fp16 ----------------
__global__ __launch_bounds__(256) void k_concatT(const float* __restrict__ img,
                                                 const float* __restrict__ exe) {
    __shared__ float tile[32][33];
    int b = blockIdx.z;
    int n0 = blockIdx.x * 32, c0 = blockIdx.y * 32;
    int tx = threadIdx.x & 31, ty = threadIdx.x >> 5;   // 32 x 8
    #pragma unroll
    for (int j = 0; j < 4; j++) {
        int c = c0 + ty + j * 8, n = n0 + tx;
        float v;
        if (n < HW) v = img[((size_t)b * CVAL + c) * HW + n];
        else        v = (n == HW) ? 1.2f * exe[b * CVAL + c] : 0.0f;
        tile[ty + j * 8][tx] = v;
    }
    __syncthreads();
    #pragma unroll
    for (int j = 0; j < 4; j++) {
        int n = n0 + ty + j * 8, c = c0 + tx;
        float v = tile[tx][ty + j * 8];
        size_t off = ((size_t)b * NPAD + n) * CVAL + c;
        g_concatT[off] = v;
        __half hi = __float2half(v);
        g_concatTh[off] = hi;
        g_concatTl[off] = __float2half(v - __half2float(hi));
    }
}

// ---------------- B prep: Bs[k][j] = sim[k][j] (j<256) | vw[j-256][k], hi/lo ----------------
__global__ __launch_bounds__(256) void k_prepB(const float* __restrict__ sim,
                                               const float* __restrict__ vw) {
    int idx = blockIdx.x * 256 + threadIdx.x;          // 131072 elems
    int k = idx >> 9, j = idx & (NB - 1);
    float v = (j < CVAL) ? sim[k * CVAL + j] : vw[(j - CVAL) * CVAL + k];
    __half hi = __float2half(v);
    g_Bh[idx] = hi;
    g_Bl[idx] = __float2half(v - __half2float(hi));
}

// ---------------- fused proj+values GEMM: split-fp16 tensor, fp32 accum ----------------
// C[m][j] = sum_k concatT[m][k] * Bs[k][j];  j<256 -> proj, j>=256 -> values
#define PV_ALD 40          // A stage [32m][40], hi+lo
#define PV_BLD 264         // B stage [32k][264], hi+lo
#define PV_AH_SZ (32 * PV_ALD * 2)
#define PV_B_SZ  (32 * PV_BLD * 2)
#define PV_STG   (2 * PV_AH_SZ + 2 * PV_B_SZ)     // hi+lo A, hi+lo B = 38912 B
#define PV_SMEM  (2 * PV_STG)                     // 77824 B -> 2 CTAs/SM
#define PV_FRAG_LD 24

__global__ __launch_bounds__(128, 2) void k_pv() {
    extern __shared__ __align__(16) char sm[];
    int b = blockIdx.z, bx = blockIdx.x;
    int j0 = bx * 256, m0 = blockIdx.y * 32;
    const __half* Ah = g_concatTh + (size_t)b * NPAD * CVAL;
    const __half* Al = g_concatTl + (size_t)b * NPAD * CVAL;
    int t = threadIdx.x, w = t >> 5, lane = t & 31;   // warp w owns j-slice w*64

    wmma::fragment<wmma::accumulator, 16, 16, 16, float> acc[2][4];
    #pragma unroll
    for (int i = 0; i < 2; i++)
        #pragma unroll
        for (int j = 0; j < 4; j++)
            wmma::fill_fragment(acc[i][j], 0.0f);

    // stage offsets within one stage: AH | AL | BH | BL
    #define PV_ISSUE(ST, K0) do {                                                        \
        char* base_ = sm + (ST) * PV_STG;                                                \
        __half* AH_ = (__half*)base_;                                                    \
        __half* AL_ = (__half*)(base_ + PV_AH_SZ);                                       \
        __half* BH_ = (__half*)(base_ + 2 * PV_AH_SZ);                                   \
        __half* BL_ = (__half*)(base_ + 2 * PV_AH_SZ + PV_B_SZ);                         \
        { int r_ = t >> 2, c_ = t & 3;                                                   \
          size_t so_ = (size_t)(m0 + r_) * CVAL + (K0) + c_ * 8;                         \
          cpa16(AH_ + r_ * PV_ALD + c_ * 8, Ah + so_);                                   \
          cpa16(AL_ + r_ * PV_ALD + c_ * 8, Al + so_); }                                 \
        _Pragma("unroll")                                                                \
        for (int i_ = 0; i_ < 8; i_++) {                                                 \
            int s_ = t + i_ * 128;                                                       \
            int r_ = s_ >> 5, c_ = s_ & 31;                                              \
            size_t so_ = (size_t)((K0) + r_) * NB + j0 + c_ * 8;                         \
            cpa16(BH_ + r_ * PV_BLD + c_ * 8, g_Bh + so_);                               \
            cpa16(BL_ + r_ * PV_BLD + c_ * 8, g_Bl + so_); }                             \
        asm volatile("cp.async.commit_group;\n" ::: "memory");                           \
    } while (0)

    PV_ISSUE(0, 0);
    PV_ISSUE(1, 32);
    #pragma unroll
    for (int ks = 0; ks < 8; ks++) {
        int st = ks & 1;
        if (ks < 7) asm volatile("cp.async.wait_group 1;\n" ::: "memory");
        else        asm volatile("cp.async.wait_group 0;\n" ::: "memory");
        __syncthreads();
        char* base_ = sm + st * PV_STG;
        const __half* AH_ = (const __half*)base_;
        const __half* AL_ = (const __half*)(base_ + PV_AH_SZ);
        const __half* BH_ = (const __half*)(base_ + 2 * PV_AH_SZ);
        const __half* BL_ = (const __half*)(base_ + 2 * PV_AH_SZ + PV_B_SZ);
        #pragma unroll
        for (int kk = 0; kk < 2; kk++) {
            wmma::fragment<wmma::matrix_a, 16, 16, 16, __half, wmma::row_major> ah[2], al[2];
            wmma::fragment<wmma::matrix_b, 16, 16, 16, __half, wmma::row_major> bh[4], bl[4];
            #pragma unroll
            for (int i = 0; i < 2; i++) {
                wmma::load_matrix_sync(ah[i], AH_ + (i * 16) * PV_ALD + kk * 16, PV_ALD);
                wmma::load_matrix_sync(al[i], AL_ + (i * 16) * PV_ALD + kk * 16, PV_ALD);
            }
            #pragma unroll
            for (int j = 0; j < 4; j++) {
                wmma::load_matrix_sync(bh[j], BH_ + (kk * 16) * PV_BLD + w * 64 + j * 16, PV_BLD);
                wmma::load_matrix_sync(bl[j], BL_ + (kk * 16) * PV_BLD + w * 64 + j * 16, PV_BLD);
            }
            #pragma unroll
            for (int i = 0; i < 2; i++)
                #pragma unroll
                for (int j = 0; j < 4; j++) {
                    wmma::mma_sync(acc[i][j], ah[i], bh[j], acc[i][j]);
                    wmma::mma_sync(acc[i][j], ah[i], bl[j], acc[i][j]);
                    wmma::mma_sync(acc[i][j], al[i], bh[j], acc[i][j]);
                }
        }
        __syncthreads();
        if (ks < 6) PV_ISSUE(st, (ks + 2) * 32);
    }

    // -------- epilogue: write proj fp32+fp16 / values fp32 (reuse stage smem) --------
    __syncthreads();
    float* fragbuf = (float*)sm + w * (16 * PV_FRAG_LD);   // 4 warps x 1536 B
    int lr = lane & 15, lh = lane >> 4;
    #pragma unroll
    for (int i = 0; i < 2; i++) {
        int m = m0 + i * 16 + lr;
        #pragma unroll
        for (int j = 0; j < 4; j++) {
            wmma::store_matrix_sync(fragbuf, acc[i][j], PV_FRAG_LD, wmma::mem_row_major);
            __syncwarp();
            const float* fr = fragbuf + lr * PV_FRAG_LD + lh * 8;
            int gj = j0 + w * 64 + j * 16 + lh * 8;
            float4 v0 = *(const float4*)fr;
            float4 v1 = *(const float4*)(fr + 4);
            if (gj < CVAL) {
                size_t off = ((size_t)b * HW + m) * CVAL + gj;
                *(float4*)&g_proj[off]     = v0;
                *(float4*)&g_proj[off + 4] = v1;
                __half2 h0 = __floats2half2_rn(v0.x, v0.y);
                __half2 h1 = __floats2half2_rn(v0.z, v0.w);
                __half2 h2 = __floats2half2_rn(v1.x, v1.y);
                __half2 h3 = __floats2half2_rn(v1.z, v1.w);
                uint4 u = make_uint4(*(unsigned*)&h0, *(unsigned*)&h1,
                                     *(unsigned*)&h2, *(unsigned*)&h3);
                *(uint4*)&g_projh[off] = u;
            } else {
                size_t off = ((size_t)b * NTOK + m) * CVAL + (gj - CVAL);
                *(float4*)&g_values[off]     = v0;
                *(float4*)&g_values[off + 4] = v1;
            }
            __syncwarp();
        }
    }
}

// ---------------- values last row (exe): warp-per-output, coalesced ----------------
__global__ __launch_bounds__(256) void k_vexe(const float* __restrict__ exe,
                                              const float* __restrict__ vw) {
    __shared__ float ex[256];
    int b = blockIdx.x, t = threadIdx.x;
    int warp = t >> 5, lane = t & 31;
    ex[t] = 1.2f * exe[b * 256 + t];
    __syncthreads();
    #pragma unroll
    for (int dd = 0; dd < 32; dd++) {
        int d = warp * 32 + dd;
        float part = 0.f;
        #pragma unroll
        for (int c8 = 0; c8 < 8; c8++) {
            int c = lane + c8 * 32;
            part += ex[c] * vw[d * 256 + c];
        }
        #pragma unroll
        for (int o = 16; o; o >>= 1) part += __shfl_xor_sync(0xffffffffu, part, o);
        if (lane == 0) g_values[((size_t)b * NTOK + HW) * CVAL + d] = part;
    }
}

// ---------------- exact fp32 exe column (for top-k) ----------------
__global__ __launch_bounds__(256) void k_execol(const float* __restrict__ exe) {
    int warp = threadIdx.x >> 5, lane = threadIdx.x & 31;
    int b = blockIdx.y;
    int m = blockIdx.x * 8 + warp;
    const float* pr = g_proj + ((size_t)b * HW + m) * CVAL;
    const float* ex = exe + b * CVAL;
    float part = 0.f;
    #pragma unroll
    for (int c = 0; c < 8; c++) {
        int cc = lane + c * 32;
        part += pr[cc] * ex[cc];
    }
    #pragma unroll
    for (int o = 16; o; o >>= 1) part += __shfl_xor_sync(0xffffffffu, part, o);
    if (lane == 0) g_attn_exe[(size_t)b * HW + m] = 1.2f * part;
}

// ---------------- attn GEMM (fp16 wmma + fp16 accum, 64x256 tile, 3 CTAs/SM) ------------
#define A_LD 40
#define B_LD 264
#define ASZ  (64 * A_LD * 2)
#define BSZ  (32 * B_LD * 2)
#define STG  (ASZ + BSZ)
#define ATTN_SMEM (3 * STG)
#define FRAG_LD 32

__global__ __launch_bounds__(128, 3) void k_attn() {
    extern __shared__ __align__(16) char sm[];
    int b = blockIdx.z, bx = blockIdx.x;
    int n0 = bx * 256, m0 = blockIdx.y * 64;
    const __half* A  = g_projh   + (size_t)b * HW * CVAL;
    const __half* Bm = g_concath + (size_t)b * CVAL * NPAD;
    int t = threadIdx.x, w = t >> 5, lane = t & 31;

    wmma::fragment<wmma::accumulator, 16, 16, 16, __half> acc[4][4];
    #pragma unroll
    for (int i = 0; i < 4; i++)
        #pragma unroll
        for (int j = 0; j < 4; j++)
            wmma::fill_fragment(acc[i][j], __float2half(0.0f));

    #define ISSUE(ST, K0) do {                                                          \
        __half* As_ = (__half*)(sm + (ST) * STG);                                       \
        __half* Bs_ = (__half*)(sm + (ST) * STG + ASZ);                                 \
        _Pragma("unroll")                                                               \
        for (int i_ = 0; i_ < 2; i_++) {                                                \
            int s_ = t + i_ * 128;                                                      \
            int r_ = s_ >> 2, c_ = s_ & 3;                                              \
            cpa16(As_ + r_ * A_LD + c_ * 8, &A[(size_t)(m0 + r_) * CVAL + (K0) + c_ * 8]); } \
        _Pragma("unroll")                                                               \
        for (int i_ = 0; i_ < 8; i_++) {                                                \
            int s_ = t + i_ * 128;                                                      \
            int r_ = s_ >> 5, c_ = s_ & 31;                                             \
            cpa16(Bs_ + r_ * B_LD + c_ * 8, &Bm[(size_t)((K0) + r_) * NPAD + n0 + c_ * 8]); } \
        asm volatile("cp.async.commit_group;\n" ::: "memory");                          \
    } while (0)

    ISSUE(0, 0);
    ISSUE(1, 32);
    #pragma unroll
    for (int ks = 0; ks < 8; ks++) {
        int st = ks % 3;
        if (ks < 7) asm volatile("cp.async.wait_group 1;\n" ::: "memory");
        else        asm volatile("cp.async.wait_group 0;\n" ::: "memory");
        __syncthreads();
        if (ks < 6) ISSUE((ks + 2) % 3, (ks + 2) * 32);
        const __half* As_ = (const __half*)(sm + st * STG);
        const __half* Bs_ = (const __half*)(sm + st * STG + ASZ);
        #pragma unroll
        for (int kk = 0; kk < 2; kk++) {
            wmma::fragment<wmma::matrix_a, 16, 16, 16, __half, wmma::row_major> af[4];
            wmma::fragment<wmma::matrix_b, 16, 16, 16, __half, wmma::row_major> bf[4];
            #pragma unroll
            for (int i = 0; i < 4; i++)
                wmma::load_matrix_sync(af[i], As_ + (i * 16) * A_LD + kk * 16, A_LD);
            #pragma unroll
            for (int j = 0; j < 4; j++)
                wmma::load_matrix_sync(bf[j], Bs_ + (kk * 16) * B_LD + w * 64 + j * 16, B_LD);
            #pragma unroll
            for (int i = 0; i < 4; i++)
                #pragma unroll
                for (int j = 0; j < 4; j++)
                    wmma::mma_sync(acc[i][j], af[i], bf[j], acc[i][j]);
        }
    }

    __syncthreads();
    __half* fragbuf = (__half*)sm + w * (16 * FRAG_LD);
    float* rowmaxp = (float*)(sm + 4 * 16 * FRAG_LD * 2);
    int lr = lane & 15, lh = lane >> 4;
    bool lastT = (bx == NTILES - 1);
    #pragma unroll
    for (int i = 0; i < 4; i++) {
        int mloc = i * 16 + lr;
        size_t grow = ((size_t)b * HW + m0 + mloc) * NPAD;
        float mj = -INFINITY;
        #pragma unroll
        for (int j = 0; j < 4; j++) {
            wmma::store_matrix_sync(fragbuf, acc[i][j], FRAG_LD, wmma::mem_row_major);
            __syncwarp();
            const __half* fr = fragbuf + lr * FRAG_LD + lh * 8;
            int gc = n0 + w * 64 + j * 16 + lh * 8;
            unsigned u[4];
            #pragma unroll
            for (int p = 0; p < 4; p++) {
                __half2 hp = *(const __half2*)(fr + p * 2);
                float2 f = __half22float2(hp);
                if (lastT) {
                    if (gc + p * 2     > HW) { f.x = -INFINITY; hp.x = __float2half(-INFINITY); }
                    if (gc + p * 2 + 1 > HW) { f.y = -INFINITY; hp.y = __float2half(-INFINITY); }
                }
                mj = fmaxf(mj, fmaxf(f.x, f.y));
                u[p] = *(unsigned*)&hp;
            }
            *(uint4*)(g_attnh + grow + gc) = make_uint4(u[0], u[1], u[2], u[3]);
            __syncwarp();
        }
        float omx = __shfl_xor_sync(0xffffffffu, mj, 16);
        mj = fmaxf(mj, omx);
        if (lh == 0) rowmaxp[mloc * 4 + w] = mj;
    }
    __syncthreads();
    if (t < 64) {
        float m4 = fmaxf(fmaxf(rowmaxp[t * 4 + 0], rowmaxp[t * 4 + 1]),
                         fmaxf(rowmaxp[t * 4 + 2], rowmaxp[t * 4 + 3]));
        g_tilemax[((size_t)b * HW + m0 + t) * NTILES + bx] = m4;
    }
}

// ---------------- top-k (exact, jax tie rule) + query gather, 1024 threads ----------------
__global__ __launch_bounds__(1024) void k_topk(float* __restrict__ out) {
    __shared__ float sv[HW];
    __shared__ int   qids[TOPKN];
    __shared__ float rv[32];
    __shared__ int   ri[32];
    int b = blockIdx.x, t = threadIdx.x;
    int warp = t >> 5, lane = t & 31;
    for (int i = t; i < HW; i += 1024)
        sv[i] = g_attn_exe[(size_t)b * HW + i];
    __syncthreads();
    for (int j = 0; j < TOPKN; j++) {
        float bv = -3.4e38f; int bi = 1 << 30;
        #pragma unroll
        for (int q = 0; q < 4; q++) {
            int i = t + q * 1024;
            float v = sv[i];
            if (v > bv || (v == bv && i < bi)) { bv = v; bi = i; }
        }
        #pragma unroll
        for (int o = 16; o; o >>= 1) {
            float ov = __shfl_down_sync(0xffffffffu, bv, o);
            int   oi = __shfl_down_sync(0xffffffffu, bi, o);
            if (ov > bv || (ov == bv && oi < bi)) { bv = ov; bi = oi; }
        }
        if (lane == 0) { rv[warp] = bv; ri[warp] = bi; }
        __syncthreads();
        if (warp == 0) {
            float fv = rv[lane]; int fi = ri[lane];
            #pragma unroll
            for (int o = 16; o; o >>= 1) {
                float ov = __shfl_down_sync(0xffffffffu, fv, o);
                int   oi = __shfl_down_sync(0xffffffffu, fi, o);
                if (ov > fv || (ov == fv && oi < fi)) { fv = ov; fi = oi; }
            }
            if (lane == 0) {
                qids[j] = fi;
                sv[fi] = -3.4e38f;
            }
        }
        __syncthreads();
    }
    for (int idx = t; idx < TOPKN * 256; idx += 1024) {
        int j = idx >> 8, d = idx & 255;
        out[QOFF + ((size_t)(b * TOPKN + j)) * 256 + d] =
            g_values[((size_t)b * NTOK + qids[j]) * 256 + d];
    }
}

// ---------------- fused softmax + sparse PV (tile-skip, exact recompute) --------
__global__ __launch_bounds__(256) void k_smpv(float* __restrict__ out) {
    int warp = threadIdx.x >> 5, lane = threadIdx.x & 31;
    size_t row = (size_t)blockIdx.x * 8 + warp;
    int b = (int)(row >> 12);

    const float* tm = g_tilemax + row * NTILES;
    float mxl = (lane < NTILES) ? tm[lane] : -INFINITY;
    float mx = mxl;
    #pragma unroll
    for (int o = 16; o; o >>= 1) mx = fmaxf(mx, __shfl_xor_sync(0xffffffffu, mx, o));
    float thr = mx - 46.0f;

    float4 o0 = make_float4(0.f, 0.f, 0.f, 0.f);
    float4 o1 = make_float4(0.f, 0.f, 0.f, 0.f);
    float sum = 0.f;
    const float* Vb = g_values  + (size_t)b * NTOK * CVAL;
    const float* pr = g_proj    + row * CVAL;
    const float* cT = g_concatT + (size_t)b * NPAD * CVAL;
    const uint4* rp = (const uint4*)(g_attnh + row * NPAD);

    #pragma unroll 1
    for (int i = 0; i < NTILES; i++) {
        float tmax = __shfl_sync(0xffffffffu, mxl, i);
        if (tmax <= thr) continue;
        uint4 u = rp[i * 32 + lane];
        float2 f0 = __half22float2(*(__half2*)&u.x);
        float2 f1 = __half22float2(*(__half2*)&u.y);
        float2 f2 = __half22float2(*(__half2*)&u.z);
        float2 f3 = __half22float2(*(__half2*)&u.w);
        bool pred = (f0.x > thr) | (f0.y > thr) | (f1.x > thr) | (f1.y > thr) |
                    (f2.x > thr) | (f2.y > thr) | (f3.x > thr) | (f3.y > thr);
        unsigned bal = __ballot_sync(0xffffffffu, pred);
        while (bal) {
            int src = __ffs(bal) - 1;
            bal &= bal - 1;
            unsigned su[4];
            su[0] = __shfl_sync(0xffffffffu, u.x, src);
            su[1] = __shfl_sync(0xffffffffu, u.y, src);
            su[2] = __shfl_sync(0xffffffffu, u.z, src);
            su[3] = __shfl_sync(0xffffffffu, u.w, src);
            int nb = (i * 32 + src) * 8;
            #pragma unroll
            for (int p = 0; p < 4; p++) {
                float2 fp = __half22float2(*(__half2*)&su[p]);
                float sv2[2] = {fp.x, fp.y};
                #pragma unroll
                for (int e = 0; e < 2; e++) {
                    if (sv2[e] > thr) {
                        int n = nb + p * 2 + e;
                        const float* cn = cT + (size_t)n * CVAL;
                        float part = 0.f;
                        #pragma unroll
                        for (int cc = 0; cc < 8; cc++) {
                            int k = lane + cc * 32;
                            part += pr[k] * cn[k];
                        }
                        #pragma unroll
                        for (int o = 16; o; o >>= 1)
                            part += __shfl_xor_sync(0xffffffffu, part, o);
                        float pw = __expf(part - mx);
                        sum += pw;
                        const float4* Vr = (const float4*)(Vb + (size_t)n * CVAL);
                        float4 v0 = Vr[lane * 2], v1 = Vr[lane * 2 + 1];
                        o0.x += pw * v0.x; o0.y += pw * v0.y; o0.z += pw * v0.z; o0.w += pw * v0.w;
                        o1.x += pw * v1.x; o1.y += pw * v1.y; o1.z += pw * v1.z; o1.w += pw * v1.w;
                    }
                }
            }
        }
    }
    float inv = 1.0f / sum;
    o0.x *= inv; o0.y *= inv; o0.z *= inv; o0.w *= inv;
    o1.x *= inv; o1.y *= inv; o1.z *= inv; o1.w *= inv;
    float4* op = (float4*)(out + row * CVAL);
    op[lane * 2] = o0;
    op[lane * 2 + 1] = o1;
}

// ---------------- launch ----------------
extern "C" void kernel_launch(void* const* d_in, const int* in_sizes, int n_in,
                              void* d_out, int out_size) {
    const float* img = (const float*)d_in[0];
    const float* exe = (const float*)d_in[1];
    const float* sim = (const float*)d_in[2];
    const float* vw  = (const float*)d_in[3];
    float* out = (float*)d_out;

    cudaFuncSetAttribute(k_attn, cudaFuncAttributeMaxDynamicSharedMemorySize, ATTN_SMEM);
    cudaFuncSetAttribute(k_pv,   cudaFuncAttributeMaxDynamicSharedMemorySize, PV_SMEM);

    {
        size_t tot = (size_t)BVAL * CVAL * (NPAD / 4);
        int blk = (int)((tot + 255) / 256);
        k_concatH<<<blk, 256>>>(img, exe);                            // 0
    }
    k_concatT<<<dim3(NPAD / 32, CVAL / 32, BVAL), 256>>>(img, exe);   // 1
    k_prepB<<<CVAL * NB / 256, 256>>>(sim, vw);                       // 2
    k_pv<<<dim3(2, 128, 8), 128, PV_SMEM>>>();                        // 3: PROFILED SLOT
    k_attn<<<dim3(NTILES, 64, 8), 128, ATTN_SMEM>>>();                // 4
    k_vexe<<<8, 256>>>(exe, vw);                                      // 5
    k_execol<<<dim3(512, 8), 256>>>(exe);                             // 6
    k_topk<<<8, 1024>>>(out);                                         // 7
    k_smpv<<<4096, 256>>>(out);                                       // 8
}